// round 9
// baseline (speedup 1.0000x reference)
#include <cuda_runtime.h>
#include <cstdint>

// Spatial correlation sampler: out[b, dh*9+dw, h, w] =
//   (1/C) * sum_c in1[b,c,h,w] * in2[b,c,h+dh-4,w+dw-4]   (zero-padded)
// B=8, C=256, H=128, W=256, patch=9.
//
// R9: R4 compute body; loading via cp.async.bulk (warp 0, 96 DMAs/stage of
// 128-160B) signaling mbarrier expect_tx. No __syncthreads in main loop:
// consumers wait full-barrier parity, arrive (1 lane/warp) on empty barrier.
// Ring of 4 stages, prefetch distance 2. OOB = size-clamped copies over a
// pre-zeroed ring (gap geometry is stage-invariant, never overwritten).

#define BB   8
#define CC_  256
#define HH   128
#define WW   256
#define RAD  4
#define PATCH 9

#define TH   8
#define TW   32
#define CCH  4                         // channels per stage
#define NSTAGE 4                       // ring depth
#define ROWS2 (TH + 2*RAD)             // 16 in2 rows
#define P2   40                        // in2 row pitch (floats), exactly 40
#define P1   32                        // in1 row pitch
#define IN2F (ROWS2 * P2)              // 640 floats per channel... per-ch tile = 16*40
#define CH2F (ROWS2 * P2)              // 640
#define IN2REGF (CCH * CH2F)           // 2560 floats (in2 region per stage)
#define CH1F (TH * P1)                 // 256
#define STAGEF (IN2REGF + CCH * CH1F)  // 3584 floats
#define STAGE_B (STAGEF * 4)           // 14336 bytes
#define RING_B (NSTAGE * STAGE_B)      // 57344 bytes
#define RING_F (NSTAGE * STAGEF)       // 14336 floats
#define NT   576
#define NSTEPS (CC_ / CCH)             // 64 stages
#define SMEM_TOTAL (RING_B + 64)       // + mbarriers

__device__ __forceinline__ unsigned smem_u32(const void* p) {
    return (unsigned)__cvta_generic_to_shared(p);
}
__device__ __forceinline__ void bulk_cp(unsigned dst, const void* src,
                                        unsigned bytes, unsigned mbar) {
    asm volatile(
        "cp.async.bulk.shared::cta.global.mbarrier::complete_tx::bytes "
        "[%0], [%1], %2, [%3];"
        :: "r"(dst), "l"(src), "r"(bytes), "r"(mbar) : "memory");
}
__device__ __forceinline__ void mbar_init(unsigned mbar, unsigned cnt) {
    asm volatile("mbarrier.init.shared.b64 [%0], %1;" :: "r"(mbar), "r"(cnt) : "memory");
}
__device__ __forceinline__ void mbar_expect(unsigned mbar, unsigned bytes) {
    asm volatile("mbarrier.arrive.expect_tx.shared.b64 _, [%0], %1;"
                 :: "r"(mbar), "r"(bytes) : "memory");
}
__device__ __forceinline__ void mbar_arrive(unsigned mbar) {
    asm volatile("mbarrier.arrive.shared.b64 _, [%0];" :: "r"(mbar) : "memory");
}
__device__ __forceinline__ void mbar_wait(unsigned mbar, unsigned parity) {
    asm volatile(
        "{\n\t"
        ".reg .pred P;\n\t"
        "W%=:\n\t"
        "mbarrier.try_wait.parity.acquire.cta.shared::cta.b64 P, [%0], %1, 0x989680;\n\t"
        "@P bra D%=;\n\t"
        "bra W%=;\n\t"
        "D%=:\n\t"
        "}"
        :: "r"(mbar), "r"(parity) : "memory");
}

__global__ void __launch_bounds__(NT, 1)
corr_kernel(const float* __restrict__ in1,
            const float* __restrict__ in2,
            float* __restrict__ out)
{
    extern __shared__ __align__(16) float sm[];   // SMEM_TOTAL bytes

    const int tid  = threadIdx.x;
    const int lane = tid & 31;
    const int warp = tid >> 5;
    const int wg   = tid & 7;          // 8 w-groups x 4 px = 32 w
    const int hh   = (tid >> 3) & 7;   // row within tile
    const int dh   = tid >> 6;         // displacement row 0..8

    const int w0 = blockIdx.x * TW;
    const int h0 = blockIdx.y * TH;
    const int b  = blockIdx.z;

    const float* __restrict__ in1b = in1 + (size_t)b * CC_ * HH * WW;
    const float* __restrict__ in2b = in2 + (size_t)b * CC_ * HH * WW;

    const unsigned smbase = smem_u32(sm);
    const unsigned mb     = smbase + RING_B;       // 4 full (8B) then 4 empty
    const unsigned ringend = smbase + RING_B;

    // ---- barriers ----
    if (tid < NSTAGE) {
        mbar_init(mb + tid * 8, 1);                // full[k]: expect_tx poster
        mbar_init(mb + 32 + tid * 8, 18);          // empty[k]: 1 arrive per warp
    }
    // ---- pre-zero ring (covers all OOB gaps; geometry stage-invariant) ----
    for (int i = tid; i < RING_F; i += NT) sm[i] = 0.0f;
    asm volatile("fence.proxy.async;" ::: "memory");
    __syncthreads();

    // ---- producer descriptors: warp 0, lane l owns copies l, l+32, l+64 ----
    // i in [0,64): in2, ch=i/16, row=i%16 ;  i in [64,96): in1, ch=(i-64)/8, row=(i-64)%8
    const float* psrc[3]; unsigned pdst[3]; unsigned psz[3];
    {
        const int lo = (w0 == 0) ? 1 : 0;
        const int hi = (w0 + TW == WW) ? 1 : 0;
#pragma unroll
        for (int t = 0; t < 2; t++) {              // two in2 descriptors
            int i  = lane + t * 32;
            int ch = i >> 4;
            int r  = i & 15;
            int gh = h0 - RAD + r;
            unsigned sz = (gh < 0 || gh >= HH) ? 0u : (unsigned)((10 - lo - hi) * 16);
            psrc[t] = in2b + ((size_t)ch * HH + (gh < 0 ? 0 : (gh >= HH ? HH - 1 : gh))) * WW
                           + (w0 - RAD + lo * 4);
            pdst[t] = smbase + (unsigned)(ch * CH2F + r * P2 + lo * 4) * 4u;
            psz[t]  = sz;
        }
        {
            int ch = lane >> 3;
            int r  = lane & 7;
            psrc[2] = in1b + ((size_t)ch * HH + (h0 + r)) * WW + w0;
            pdst[2] = smbase + (unsigned)(IN2REGF + ch * CH1F + r * P1) * 4u;
            psz[2]  = 128u;
        }
    }
    // total expect_tx bytes per stage (same every stage)
    unsigned exp_bytes = psz[0] + psz[1] + psz[2];
#pragma unroll
    for (int m = 16; m > 0; m >>= 1)
        exp_bytes += __shfl_xor_sync(0xFFFFFFFFu, exp_bytes, m);

    const size_t src_step = (size_t)CCH * HH * WW;   // floats per stage

    // issue one stage into the slot currently pointed to by pdst[]
    auto issue_stage = [&](int slot) {
        if (lane == 0) mbar_expect(mb + slot * 8, exp_bytes);
        __syncwarp();
#pragma unroll
        for (int t = 0; t < 3; t++) {
            if (psz[t] > 0) bulk_cp(pdst[t], psrc[t], psz[t], mb + slot * 8);
            psrc[t] += src_step;
            pdst[t] += STAGE_B; if (pdst[t] >= ringend) pdst[t] -= RING_B;
        }
    };

    // ---- accumulators ----
    float acc[PATCH][4];
#pragma unroll
    for (int dw = 0; dw < PATCH; dw++)
#pragma unroll
        for (int j = 0; j < 4; j++) acc[dw][j] = 0.0f;

    const int off_win = (hh + dh) * P2 + wg * 4;       // within a channel's in2 tile
    const int off_a   = IN2REGF + hh * P1 + wg * 4;    // within in1 region

    // ---- prologue loads: stages 0,1 -> slots 0,1 ----
    if (warp == 0) {
        issue_stage(0);
        issue_stage(1);
    }

    // ---- main loop: no __syncthreads ----
    for (int s = 0; s < NSTEPS; s++) {
        if (warp == 0 && s + 2 < NSTEPS) {
            const int j = (s + 2) & (NSTAGE - 1);
            if (s >= 2) mbar_wait(mb + 32 + j * 8, ((s - 2) >> 2) & 1);  // empty[j]
            issue_stage(j);
        }

        const int k = s & (NSTAGE - 1);
        mbar_wait(mb + k * 8, (s >> 2) & 1);           // full[k]
        const float* buf = sm + k * STAGEF;

#pragma unroll
        for (int cc = 0; cc < CCH; cc++) {
            const float* chp = buf + cc * CH2F;
            const float4 a4 = *(const float4*)(buf + cc * CH1F + off_a);
            const float4* wp = (const float4*)(chp + off_win);
            float4 x0 = wp[0], x1 = wp[1], x2 = wp[2];
            float win[12] = { x0.x, x0.y, x0.z, x0.w,
                              x1.x, x1.y, x1.z, x1.w,
                              x2.x, x2.y, x2.z, x2.w };
            float a[4] = { a4.x, a4.y, a4.z, a4.w };
#pragma unroll
            for (int dw = 0; dw < PATCH; dw++)
#pragma unroll
                for (int j = 0; j < 4; j++)
                    acc[dw][j] = fmaf(a[j], win[j + dw], acc[dw][j]);
        }

        __syncwarp();
        if (lane == 0) mbar_arrive(mb + 32 + k * 8);   // empty[k]
    }

    // ---- epilogue ----
    const float scale = 1.0f / (float)CC_;
    float* outp = out + (((size_t)b * (PATCH * PATCH) + dh * PATCH) * HH + (h0 + hh)) * WW
                      + (w0 + wg * 4);
#pragma unroll
    for (int dw = 0; dw < PATCH; dw++) {
        float4 v;
        v.x = acc[dw][0] * scale;
        v.y = acc[dw][1] * scale;
        v.z = acc[dw][2] * scale;
        v.w = acc[dw][3] * scale;
        *(float4*)(outp + (size_t)dw * HH * WW) = v;
    }
}

extern "C" void kernel_launch(void* const* d_in, const int* in_sizes, int n_in,
                              void* d_out, int out_size)
{
    const float* in1 = (const float*)d_in[0];
    const float* in2 = (const float*)d_in[1];
    float* out = (float*)d_out;

    cudaFuncSetAttribute(corr_kernel,
                         cudaFuncAttributeMaxDynamicSharedMemorySize, SMEM_TOTAL);

    dim3 grid(WW / TW, HH / TH, BB);   // 8 x 16 x 8 = 1024 blocks
    dim3 block(NT);
    corr_kernel<<<grid, block, SMEM_TOTAL>>>(in1, in2, out);
}

// round 10
// speedup vs baseline: 3.8359x; 3.8359x over previous
#include <cuda_runtime.h>
#include <cstdint>

// Spatial correlation sampler: out[b, dh*9+dw, h, w] =
//   (1/C) * sum_c in1[b,c,h,w] * in2[b,c,h+dh-4,w+dw-4]   (zero-padded)
// B=8, C=256, H=128, W=256, patch=9.
//
// R10 = R4 skeleton + (a) channel-level register double-buffering so LDS of
// channel cc+1 overlaps FFMA of channel cc, (b) ring-4 pipeline with
// wait_group 2 / 3 stages in flight (61KB dynamic smem). One __syncthreads
// per stage (required: cp.async completion is per-warp; the barrier is what
// publishes other warps' chunks).

#define BB   8
#define CC_  256
#define HH   128
#define WW   256
#define RAD  4
#define PATCH 9

#define TH   8
#define TW   32
#define CCH  4                        // channels per stage
#define NSTAGE 4                      // ring depth
#define ROWS2 (TH + 2*RAD)            // 16 in2 rows
#define PITCH2 44                     // in2 row pitch (floats), 40 used
#define IN2F  (ROWS2 * PITCH2)        // 704
#define CHF   (IN2F + TH * TW)        // 960 floats per channel
#define STAGEF (CCH * CHF)            // 3840 floats
#define STAGE_B (STAGEF * 4)          // 15360 bytes
#define RING_B (NSTAGE * STAGE_B)     // 61440 bytes
#define IN2CK (ROWS2 * 11)            // 176 chunks per channel (in2)
#define CHCK  (IN2CK + TH * 8)        // 240 chunks per channel
#define TOTCK (CCH * CHCK)            // 960 chunks per stage
#define NT    576
#define NSTEPS (CC_ / CCH)            // 64 stages

__device__ __forceinline__ unsigned smem_u32(const void* p) {
    return (unsigned)__cvta_generic_to_shared(p);
}
__device__ __forceinline__ void cp16(unsigned dst, const void* src, int src_bytes) {
    asm volatile("cp.async.cg.shared.global [%0], [%1], 16, %2;\n"
                 :: "r"(dst), "l"(src), "r"(src_bytes));
}

struct ChRegs {
    float4 w0, w1, w2;   // window f0..f11
    float4 a;            // in1 pixels
};

__device__ __forceinline__ void pref_ch(const float* chp, int off_win, int off_a,
                                        ChRegs& r) {
    const float4* wp = (const float4*)(chp + off_win);
    r.w0 = wp[0];
    r.w1 = wp[1];
    r.w2 = wp[2];
    r.a  = *(const float4*)(chp + off_a);
}

__device__ __forceinline__ void body_ch(const ChRegs& r, float acc[PATCH][4]) {
    float win[12] = { r.w0.x, r.w0.y, r.w0.z, r.w0.w,
                      r.w1.x, r.w1.y, r.w1.z, r.w1.w,
                      r.w2.x, r.w2.y, r.w2.z, r.w2.w };
    float a[4] = { r.a.x, r.a.y, r.a.z, r.a.w };
#pragma unroll
    for (int dw = 0; dw < PATCH; dw++)
#pragma unroll
        for (int j = 0; j < 4; j++)
            acc[dw][j] = fmaf(a[j], win[j + dw], acc[dw][j]);
}

__global__ void __launch_bounds__(NT, 1)
corr_kernel(const float* __restrict__ in1,
            const float* __restrict__ in2,
            float* __restrict__ out)
{
    extern __shared__ __align__(16) float sm[];          // RING_B bytes dynamic

    const int tid = threadIdx.x;
    const int wg  = tid & 7;          // 8 w-groups x 4 px = 32 w
    const int hh  = (tid >> 3) & 7;   // row within tile
    const int dh  = tid >> 6;         // displacement row 0..8

    const int w0 = blockIdx.x * TW;
    const int h0 = blockIdx.y * TH;
    const int b  = blockIdx.z;

    const float* __restrict__ in1b = in1 + (size_t)b * CC_ * HH * WW;
    const float* __restrict__ in2b = in2 + (size_t)b * CC_ * HH * WW;

    // ---- hoisted loader slots (decoded once; per stage just advance) ----
    const unsigned smbase = smem_u32(sm);
    const unsigned smend  = smbase + RING_B;

    const float* src0; unsigned dst0; int sz0;
    const float* src1 = in2b; unsigned dst1 = smbase; int sz1 = 0;
    const bool has1 = (tid < TOTCK - NT);   // tid < 384 owns a 2nd chunk

    auto decode = [&](int i, const float*& src, unsigned& dst, int& sz) {
        int ch = i / CHCK;                 // channel within stage 0..3
        int r  = i - ch * CHCK;
        sz = 16;
        if (r < IN2CK) {
            int row = r / 11;
            int ck  = r - row * 11;
            int gh = h0 - RAD + row;
            int gw = w0 - RAD + ck * 4;
            dst = smbase + (unsigned)(ch * CHF + row * PITCH2 + ck * 4) * 4u;
            if (gh < 0 || gh >= HH || gw < 0 || gw >= WW) {
                sz = 0; src = in2b;        // full-chunk zero fill each stage
            } else {
                src = in2b + ((size_t)ch * HH + gh) * WW + gw;
            }
        } else {
            int r2 = r - IN2CK;
            int row = r2 >> 3;
            int ck  = r2 & 7;
            dst = smbase + (unsigned)(ch * CHF + IN2F + row * TW + ck * 4) * 4u;
            src = in1b + ((size_t)ch * HH + (h0 + row)) * WW + (w0 + ck * 4);
        }
    };

    decode(tid, src0, dst0, sz0);
    if (has1) decode(tid + NT, src1, dst1, sz1);

    auto load_stage = [&]() {
        cp16(dst0, src0, sz0);
        src0 += CCH * HH * WW;
        dst0 += STAGE_B; if (dst0 >= smend) dst0 -= RING_B;
        if (has1) {
            cp16(dst1, src1, sz1);
            src1 += CCH * HH * WW;
            dst1 += STAGE_B; if (dst1 >= smend) dst1 -= RING_B;
        }
        asm volatile("cp.async.commit_group;\n");
    };

    // ---- accumulators ----
    float acc[PATCH][4];
#pragma unroll
    for (int dw = 0; dw < PATCH; dw++)
#pragma unroll
        for (int j = 0; j < 4; j++) acc[dw][j] = 0.0f;

    const int off_win = (hh + dh) * PITCH2 + wg * 4;     // in2 window start
    const int off_a   = IN2F + hh * TW + wg * 4;         // in1 pixels

    load_stage();   // stage 0 -> slot 0
    load_stage();   // stage 1 -> slot 1
    load_stage();   // stage 2 -> slot 2

    const float* buf = sm;
    ChRegs rg0, rg1;

    for (int s = 0; s < NSTEPS; s++) {
        asm volatile("cp.async.wait_group 2;\n");        // my stage-s chunks done
        __syncthreads();                                  // publish ALL warps' stage s
        if (s + 3 < NSTEPS) load_stage();                 // stage s+3 -> slot (s+3)%4
        else asm volatile("cp.async.commit_group;\n");    // keep group accounting

        // channel-level software pipeline: LDS(cc+1) overlaps FFMA(cc)
        pref_ch(buf + 0 * CHF, off_win, off_a, rg0);
        pref_ch(buf + 1 * CHF, off_win, off_a, rg1);
        body_ch(rg0, acc);
        pref_ch(buf + 2 * CHF, off_win, off_a, rg0);
        body_ch(rg1, acc);
        pref_ch(buf + 3 * CHF, off_win, off_a, rg1);
        body_ch(rg0, acc);
        body_ch(rg1, acc);

        buf += STAGEF;
        if (buf >= sm + NSTAGE * STAGEF) buf = sm;
    }

    // ---- epilogue ----
    const float scale = 1.0f / (float)CC_;
    float* outp = out + (((size_t)b * (PATCH * PATCH) + dh * PATCH) * HH + (h0 + hh)) * WW
                      + (w0 + wg * 4);
#pragma unroll
    for (int dw = 0; dw < PATCH; dw++) {
        float4 v;
        v.x = acc[dw][0] * scale;
        v.y = acc[dw][1] * scale;
        v.z = acc[dw][2] * scale;
        v.w = acc[dw][3] * scale;
        *(float4*)(outp + (size_t)dw * HH * WW) = v;
    }
}

extern "C" void kernel_launch(void* const* d_in, const int* in_sizes, int n_in,
                              void* d_out, int out_size)
{
    const float* in1 = (const float*)d_in[0];
    const float* in2 = (const float*)d_in[1];
    float* out = (float*)d_out;

    cudaFuncSetAttribute(corr_kernel,
                         cudaFuncAttributeMaxDynamicSharedMemorySize, RING_B);

    dim3 grid(WW / TW, HH / TH, BB);   // 8 x 16 x 8 = 1024 blocks
    dim3 block(NT);
    corr_kernel<<<grid, block, RING_B>>>(in1, in2, out);
}

// round 11
// speedup vs baseline: 4.4458x; 1.1590x over previous
#include <cuda_runtime.h>
#include <cstdint>

// Spatial correlation sampler: out[b, dh*9+dw, h, w] =
//   (1/C) * sum_c in1[b,c,h,w] * in2[b,c,h+dh-4,w+dw-4]   (zero-padded)
// B=8, C=256, H=128, W=256, patch=9.
//
// R11: R4 pipeline/compute, but 288-thread CTAs (tile 8h x 16w), 2 CTAs/SM so
// barrier bubbles of one CTA are filled by the other. Conflict-free pitches
// for TW=16: P2=48 floats (12 chunks == 4 mod 8), P1=16 floats (4 chunks).

#define BB   8
#define CC_  256
#define HH   128
#define WW   256
#define RAD  4
#define PATCH 9

#define TH   8
#define TW   16
#define CCH  4                        // channels per stage
#define NSTAGE 4                      // ring depth
#define ROWS2 (TH + 2*RAD)            // 16 in2 rows
#define P2   48                       // in2 row pitch (floats); 24 used; 12 chunks
#define P1   16                       // in1 row pitch (floats); 16 used; 4 chunks
#define IN2F (ROWS2 * P2)             // 768
#define CHF  (IN2F + TH * P1)         // 896 floats per channel
#define STAGEF (CCH * CHF)            // 3584 floats
#define STAGE_B (STAGEF * 4)          // 14336 bytes
#define RING_B (NSTAGE * STAGE_B)     // 57344 bytes
#define IN2CK (ROWS2 * 6)             // 96 chunks per channel (in2: 24 floats/row)
#define CHCK  (IN2CK + TH * 4)        // 128 chunks per channel
#define TOTCK (CCH * CHCK)            // 512 chunks per stage
#define NT    288
#define NSTEPS (CC_ / CCH)            // 64 stages

__device__ __forceinline__ unsigned smem_u32(const void* p) {
    return (unsigned)__cvta_generic_to_shared(p);
}
__device__ __forceinline__ void cp16(unsigned dst, const void* src, int src_bytes) {
    asm volatile("cp.async.cg.shared.global [%0], [%1], 16, %2;\n"
                 :: "r"(dst), "l"(src), "r"(src_bytes));
}

__global__ void __launch_bounds__(NT, 2)
corr_kernel(const float* __restrict__ in1,
            const float* __restrict__ in2,
            float* __restrict__ out)
{
    extern __shared__ __align__(16) float sm[];          // RING_B bytes dynamic

    const int tid  = threadIdx.x;
    const int lane = tid & 31;
    const int wg   = lane & 3;        // 4 w-groups x 4 px = 16 w
    const int hh   = lane >> 2;       // 0..7 rows
    const int dh   = tid >> 5;        // warp id = displacement row 0..8

    const int w0 = blockIdx.x * TW;
    const int h0 = blockIdx.y * TH;
    const int b  = blockIdx.z;

    const float* __restrict__ in1b = in1 + (size_t)b * CC_ * HH * WW;
    const float* __restrict__ in2b = in2 + (size_t)b * CC_ * HH * WW;

    // ---- hoisted loader slots (decoded once; per stage just advance) ----
    const unsigned smbase = smem_u32(sm);
    const unsigned smend  = smbase + RING_B;

    const float* src0; unsigned dst0; int sz0;
    const float* src1 = in2b; unsigned dst1 = smbase; int sz1 = 0;
    const bool has1 = (tid < TOTCK - NT);   // tid < 224 owns a 2nd chunk

    auto decode = [&](int i, const float*& src, unsigned& dst, int& sz) {
        int ch = i >> 7;                   // CHCK = 128
        int r  = i & 127;
        sz = 16;
        if (r < IN2CK) {
            int row = r / 6;
            int ck  = r - row * 6;
            int gh = h0 - RAD + row;
            int gw = w0 - RAD + ck * 4;    // chunk fully in or fully out (gw%4==0)
            dst = smbase + (unsigned)(ch * CHF + row * P2 + ck * 4) * 4u;
            if (gh < 0 || gh >= HH || gw < 0 || gw >= WW) {
                sz = 0; src = in2b;        // full-chunk zero fill each stage
            } else {
                src = in2b + ((size_t)ch * HH + gh) * WW + gw;
            }
        } else {
            int r2 = r - IN2CK;
            int row = r2 >> 2;
            int ck  = r2 & 3;
            dst = smbase + (unsigned)(ch * CHF + IN2F + row * P1 + ck * 4) * 4u;
            src = in1b + ((size_t)ch * HH + (h0 + row)) * WW + (w0 + ck * 4);
        }
    };

    decode(tid, src0, dst0, sz0);
    if (has1) decode(tid + NT, src1, dst1, sz1);

    auto load_stage = [&]() {
        cp16(dst0, src0, sz0);
        src0 += CCH * HH * WW;
        dst0 += STAGE_B; if (dst0 >= smend) dst0 -= RING_B;
        if (has1) {
            cp16(dst1, src1, sz1);
            src1 += CCH * HH * WW;
            dst1 += STAGE_B; if (dst1 >= smend) dst1 -= RING_B;
        }
        asm volatile("cp.async.commit_group;\n");
    };

    // ---- accumulators ----
    float acc[PATCH][4];
#pragma unroll
    for (int dw = 0; dw < PATCH; dw++)
#pragma unroll
        for (int j = 0; j < 4; j++) acc[dw][j] = 0.0f;

    const int off_win = (hh + dh) * P2 + wg * 4;     // reads floats [wg*4, wg*4+12)
    const int off_a   = IN2F + hh * P1 + wg * 4;

    load_stage();   // stage 0 -> slot 0
    load_stage();   // stage 1 -> slot 1
    load_stage();   // stage 2 -> slot 2

    const float* buf = sm;
    for (int s = 0; s < NSTEPS; s++) {
        asm volatile("cp.async.wait_group 2;\n");        // my stage-s chunks done
        __syncthreads();                                  // publish all warps' stage s
        if (s + 3 < NSTEPS) load_stage();                 // stage s+3 -> freed slot
        else asm volatile("cp.async.commit_group;\n");    // keep group accounting

#pragma unroll
        for (int cc = 0; cc < CCH; cc++) {
            const float* chp = buf + cc * CHF;
            const float4 a4 = *(const float4*)(chp + off_a);
            const float4* wp = (const float4*)(chp + off_win);
            float4 x0 = wp[0], x1 = wp[1], x2 = wp[2];
            float win[12] = { x0.x, x0.y, x0.z, x0.w,
                              x1.x, x1.y, x1.z, x1.w,
                              x2.x, x2.y, x2.z, x2.w };
            float a[4] = { a4.x, a4.y, a4.z, a4.w };
#pragma unroll
            for (int dw = 0; dw < PATCH; dw++)
#pragma unroll
                for (int j = 0; j < 4; j++)
                    acc[dw][j] = fmaf(a[j], win[j + dw], acc[dw][j]);
        }

        buf += STAGEF;
        if (buf >= sm + NSTAGE * STAGEF) buf = sm;
    }

    // ---- epilogue ----
    const float scale = 1.0f / (float)CC_;
    float* outp = out + (((size_t)b * (PATCH * PATCH) + dh * PATCH) * HH + (h0 + hh)) * WW
                      + (w0 + wg * 4);
#pragma unroll
    for (int dw = 0; dw < PATCH; dw++) {
        float4 v;
        v.x = acc[dw][0] * scale;
        v.y = acc[dw][1] * scale;
        v.z = acc[dw][2] * scale;
        v.w = acc[dw][3] * scale;
        *(float4*)(outp + (size_t)dw * HH * WW) = v;
    }
}

extern "C" void kernel_launch(void* const* d_in, const int* in_sizes, int n_in,
                              void* d_out, int out_size)
{
    const float* in1 = (const float*)d_in[0];
    const float* in2 = (const float*)d_in[1];
    float* out = (float*)d_out;

    cudaFuncSetAttribute(corr_kernel,
                         cudaFuncAttributeMaxDynamicSharedMemorySize, RING_B);

    dim3 grid(WW / TW, HH / TH, BB);   // 16 x 16 x 8 = 2048 blocks
    dim3 block(NT);
    corr_kernel<<<grid, block, RING_B>>>(in1, in2, out);
}